// round 5
// baseline (speedup 1.0000x reference)
#include <cuda_runtime.h>
#include <cuda_fp16.h>
#include <math.h>

#define NN 100000
#define NE 1600000
#define DF 64
#define NTILES (NN / 16)
#define WS 66        // padded W row stride (floats): conflict-free float2 LDS
#define SCB 98       // scan blocks: ceil(NN/1024)

// ---------------- device scratch (static: no allocation allowed) ----------------
__device__ __half g_UVf[NN * 128];  // per node: U[0:64] then Vf[0:64]  (fp16)
__device__ __half g_UVt[NN * 128];  // per node: U[0:64] then Vt[0:64]  (fp16)
__device__ float g_outinv[NN];
__device__ float g_ininv [NN];
__device__ int   g_degout[NN];
__device__ int   g_degin [NN];
__device__ int   g_rs_fwd[NN + 1];
__device__ int   g_rs_rev[NN + 1];
__device__ int   g_cur_fwd[NN];
__device__ int   g_cur_rev[NN];
__device__ int   g_csr_fwd[NE];
__device__ int   g_csr_rev[NE];
__device__ int   g_bsum_fwd[SCB];
__device__ int   g_bsum_rev[SCB];
__device__ int   g_bbase_fwd[SCB];
__device__ int   g_bbase_rev[SCB];
__device__ float g_Wr[DF * DF];
__device__ float g_Wi[DF * DF];
__device__ float g_bias[128];      // [0:64) breal_eff, [64:128) bimag_eff

// ---------------- helpers ----------------
__device__ __forceinline__ void ffma2(unsigned long long& acc,
                                      unsigned long long a,
                                      unsigned long long b) {
    asm("fma.rn.f32x2 %0, %1, %2, %0;" : "+l"(acc) : "l"(a), "l"(b));
}

__device__ __forceinline__ float2 unpack2(unsigned long long v) {
    float2 r;
    asm("mov.b64 {%0, %1}, %2;" : "=f"(r.x), "=f"(r.y) : "l"(v));
    return r;
}

__device__ __forceinline__ void acc_fma(float4& acc, float w, uint2 pk) {
    float2 f0 = __half22float2(*(const __half2*)&pk.x);
    float2 f1 = __half22float2(*(const __half2*)&pk.y);
    acc.x = fmaf(w, f0.x, acc.x); acc.y = fmaf(w, f0.y, acc.y);
    acc.z = fmaf(w, f1.x, acc.z); acc.w = fmaf(w, f1.y, acc.w);
}

// ---------------- kernels ----------------
// (L1) zero degree counters + build effective weights/biases
__global__ void k_zero_weights(const float* __restrict__ Wr, const float* __restrict__ br,
                               const float* __restrict__ Wi, const float* __restrict__ bi) {
    int i = blockIdx.x * blockDim.x + threadIdx.x;
    if (i < NN) { g_degout[i] = 0; g_degin[i] = 0; }
    if (i < DF * DF) {
        g_Wr[i] = Wr[i] + 0.5f * Wr[4096 + i] + 0.25f * Wr[8192 + i];
        g_Wi[i] = Wi[i] + 0.5f * Wi[4096 + i] + 0.25f * Wi[8192 + i];
    }
    if (i < DF) {
        float bre = br[i] + 0.5f * br[64 + i] + 0.25f * br[128 + i];
        float bie = bi[i] + 0.5f * bi[64 + i] + 0.25f * bi[128 + i];
        g_bias[i]      = bre - bie;
        g_bias[64 + i] = bre + bie;
    }
}

// (L2) degree counting
__global__ void k_deg(const int* __restrict__ ei) {
    int i = blockIdx.x * blockDim.x + threadIdx.x;
    if (i < NE) {
        atomicAdd(&g_degout[ei[i]], 1);
        atomicAdd(&g_degin [ei[NE + i]], 1);
    }
}

// (L3) per-block degree sums + deg^-0.25 normalizers (fused)
__global__ __launch_bounds__(1024) void k_bsum_inv() {
    __shared__ int sf[1024], sr[1024];
    int t = threadIdx.x;
    int i = blockIdx.x * 1024 + t;
    int dout = 0, din = 0;
    if (i < NN) {
        dout = g_degout[i];
        din  = g_degin[i];
        g_outinv[i] = (dout > 0) ? rsqrtf(sqrtf((float)dout)) : 0.0f;
        g_ininv [i] = (din  > 0) ? rsqrtf(sqrtf((float)din )) : 0.0f;
    }
    sf[t] = dout; sr[t] = din;
    __syncthreads();
    for (int off = 512; off > 0; off >>= 1) {
        if (t < off) { sf[t] += sf[t + off]; sr[t] += sr[t + off]; }
        __syncthreads();
    }
    if (t == 0) {
        g_bsum_fwd[blockIdx.x] = sf[0];
        g_bsum_rev[blockIdx.x] = sr[0];
    }
}

// (L4) Fused dense transform -> fp16 interleaved node vectors
//   a = xr@Wr, b = xi@Wi, q = xi@Wr, r = xr@Wi
//   U = 0.5(a-b), Vt = 0.5q, Vf = r + 0.5q
__global__ __launch_bounds__(256) void k_transform(const float* __restrict__ xr,
                                                   const float* __restrict__ xi) {
    __shared__ __align__(16) float sWr[DF * WS];
    __shared__ __align__(16) float sWi[DF * WS];
    __shared__ __align__(16) float sx[16 * 2 * DF];

    int t = threadIdx.x;
    for (int i = t; i < DF * DF; i += 256) {
        int o = i >> 6, d = i & 63;
        sWr[o * WS + d] = g_Wr[i];
        sWi[o * WS + d] = g_Wi[i];
    }
    __syncthreads();

    int node = t >> 4;
    int oq   = t & 15;

    for (int tile = blockIdx.x; tile < NTILES; tile += gridDim.x) {
        int nbase = tile * 16;
        for (int i = t; i < 512; i += 256) {
            int nd = i >> 5;
            int k  = i & 31;
            float4 v = (k < 16) ? ((const float4*)xr)[(size_t)(nbase + nd) * 16 + k]
                                : ((const float4*)xi)[(size_t)(nbase + nd) * 16 + (k - 16)];
            ((float4*)sx)[nd * 32 + k] = v;
        }
        __syncthreads();

        unsigned long long accA[4] = {0,0,0,0}, accB[4] = {0,0,0,0};
        unsigned long long accQ[4] = {0,0,0,0}, accR[4] = {0,0,0,0};
        const unsigned long long* xrp = (const unsigned long long*)(sx + node * 128);
        const unsigned long long* xip = (const unsigned long long*)(sx + node * 128 + 64);

        #pragma unroll 8
        for (int d2 = 0; d2 < 32; d2++) {
            unsigned long long x_r = xrp[d2];
            unsigned long long x_i = xip[d2];
            #pragma unroll
            for (int j = 0; j < 4; j++) {
                int o = oq + j * 16;
                unsigned long long wr = *(const unsigned long long*)(sWr + o * WS + 2 * d2);
                unsigned long long wi = *(const unsigned long long*)(sWi + o * WS + 2 * d2);
                ffma2(accA[j], x_r, wr);
                ffma2(accB[j], x_i, wi);
                ffma2(accQ[j], x_i, wr);
                ffma2(accR[j], x_r, wi);
            }
        }

        size_t nb = (size_t)(nbase + node) * 128;
        #pragma unroll
        for (int j = 0; j < 4; j++) {
            float2 fa = unpack2(accA[j]);
            float2 fb = unpack2(accB[j]);
            float2 fq = unpack2(accQ[j]);
            float2 fr = unpack2(accR[j]);
            float a = fa.x + fa.y, b = fb.x + fb.y;
            float q = fq.x + fq.y, r = fr.x + fr.y;
            int o = oq + j * 16;
            __half hU  = __float2half_rn(0.5f * (a - b));
            __half hVf = __float2half_rn(r + 0.5f * q);
            __half hVt = __float2half_rn(0.5f * q);
            g_UVf[nb + o]      = hU;
            g_UVf[nb + 64 + o] = hVf;
            g_UVt[nb + o]      = hU;
            g_UVt[nb + 64 + o] = hVt;
        }
        __syncthreads();
    }
}

// (L5) scan stage 2: exclusive scan of the 98 block sums
__global__ __launch_bounds__(128) void k_scantop() {
    __shared__ int sf[128], sr[128];
    int t = threadIdx.x;
    sf[t] = (t < SCB) ? g_bsum_fwd[t] : 0;
    sr[t] = (t < SCB) ? g_bsum_rev[t] : 0;
    __syncthreads();
    for (int off = 1; off < 128; off <<= 1) {
        int vf = sf[t], vr = sr[t];
        int af = (t >= off) ? sf[t - off] : 0;
        int ar = (t >= off) ? sr[t - off] : 0;
        __syncthreads();
        sf[t] = vf + af; sr[t] = vr + ar;
        __syncthreads();
    }
    if (t < SCB) {
        g_bbase_fwd[t] = (t == 0) ? 0 : sf[t - 1];
        g_bbase_rev[t] = (t == 0) ? 0 : sr[t - 1];
    }
}

// (L6) scan stage 3: in-block exclusive scan + block base -> rs/cur
__global__ __launch_bounds__(1024) void k_offsets() {
    __shared__ int sf[1024], sr[1024];
    int t = threadIdx.x;
    int i = blockIdx.x * 1024 + t;
    int dout = (i < NN) ? g_degout[i] : 0;
    int din  = (i < NN) ? g_degin[i]  : 0;
    sf[t] = dout; sr[t] = din;
    __syncthreads();
    for (int off = 1; off < 1024; off <<= 1) {
        int vf = sf[t], vr = sr[t];
        int af = (t >= off) ? sf[t - off] : 0;
        int ar = (t >= off) ? sr[t - off] : 0;
        __syncthreads();
        sf[t] = vf + af; sr[t] = vr + ar;
        __syncthreads();
    }
    if (i < NN) {
        int of  = g_bbase_fwd[blockIdx.x] + sf[t] - dout;
        int orv = g_bbase_rev[blockIdx.x] + sr[t] - din;
        g_rs_fwd[i] = of;  g_cur_fwd[i] = of;
        g_rs_rev[i] = orv; g_cur_rev[i] = orv;
    }
    if (i == NN - 1) { g_rs_fwd[NN] = NE; g_rs_rev[NN] = NE; }
}

// (L7) CSR placement
__global__ void k_place(const int* __restrict__ ei) {
    int e = blockIdx.x * blockDim.x + threadIdx.x;
    if (e < NE) {
        int row = ei[e];
        int col = ei[NE + e];
        int p = atomicAdd(&g_cur_fwd[row], 1);
        g_csr_fwd[p] = col;
        int q = atomicAdd(&g_cur_rev[col], 1);
        g_csr_rev[q] = row;
    }
}

// (L8) Pull-mode gather, inner loop unrolled x4 for MLP.
__global__ __launch_bounds__(256) void k_gather(float* __restrict__ out) {
    int n    = (blockIdx.x * 256 + threadIdx.x) >> 5;
    int lane = threadIdx.x & 31;
    if (n >= NN) return;

    float4 acc = ((const float4*)g_bias)[lane];
    float oinv = g_outinv[n];
    float iinv = g_ininv[n];

    #pragma unroll
    for (int pass = 0; pass < 2; pass++) {
        const int*    rs   = pass ? g_rs_rev  : g_rs_fwd;
        const int*    csr  = pass ? g_csr_rev : g_csr_fwd;
        const float*  winv = pass ? g_outinv  : g_ininv;
        const __half* V    = pass ? g_UVt     : g_UVf;
        float         self = pass ? iinv      : oinv;

        int s = __ldg(rs + n), e = __ldg(rs + n + 1);
        for (int base = s; base < e; base += 32) {
            unsigned long long ent = 0;
            if (base + lane < e) {
                int idxl = __ldg(csr + base + lane);
                float w = self * __ldg(winv + idxl);
                ent = ((unsigned long long)__float_as_uint(w) << 32) | (unsigned)idxl;
            }
            int m = min(32, e - base);
            int j = 0;
            for (; j + 4 <= m; j += 4) {
                unsigned long long v0 = __shfl_sync(0xffffffffu, ent, j);
                unsigned long long v1 = __shfl_sync(0xffffffffu, ent, j + 1);
                unsigned long long v2 = __shfl_sync(0xffffffffu, ent, j + 2);
                unsigned long long v3 = __shfl_sync(0xffffffffu, ent, j + 3);
                uint2 p0 = __ldg((const uint2*)(V + (size_t)(unsigned)(v0 & 0xffffffffu) * 128) + lane);
                uint2 p1 = __ldg((const uint2*)(V + (size_t)(unsigned)(v1 & 0xffffffffu) * 128) + lane);
                uint2 p2 = __ldg((const uint2*)(V + (size_t)(unsigned)(v2 & 0xffffffffu) * 128) + lane);
                uint2 p3 = __ldg((const uint2*)(V + (size_t)(unsigned)(v3 & 0xffffffffu) * 128) + lane);
                acc_fma(acc, __uint_as_float((unsigned)(v0 >> 32)), p0);
                acc_fma(acc, __uint_as_float((unsigned)(v1 >> 32)), p1);
                acc_fma(acc, __uint_as_float((unsigned)(v2 >> 32)), p2);
                acc_fma(acc, __uint_as_float((unsigned)(v3 >> 32)), p3);
            }
            for (; j < m; j++) {
                unsigned long long v = __shfl_sync(0xffffffffu, ent, j);
                uint2 pk = __ldg((const uint2*)(V + (size_t)(unsigned)(v & 0xffffffffu) * 128) + lane);
                acc_fma(acc, __uint_as_float((unsigned)(v >> 32)), pk);
            }
        }
    }

    if (lane < 16) {
        ((float4*)(out + (size_t)n * DF))[lane] = acc;
    } else {
        ((float4*)(out + (size_t)NN * DF + (size_t)n * DF))[lane - 16] = acc;
    }
}

// ---------------- launch ----------------
extern "C" void kernel_launch(void* const* d_in, const int* in_sizes, int n_in,
                              void* d_out, int out_size) {
    const float* xr = (const float*)d_in[0];
    const float* xi = (const float*)d_in[1];
    const int*   ei = (const int*)  d_in[2];
    const float* Wr = (const float*)d_in[3];
    const float* br = (const float*)d_in[4];
    const float* Wi = (const float*)d_in[5];
    const float* bi = (const float*)d_in[6];
    float* out = (float*)d_out;

    k_zero_weights<<<(NN + 255) / 256, 256>>>(Wr, br, Wi, bi);
    k_deg<<<(NE + 255) / 256, 256>>>(ei);
    k_bsum_inv<<<SCB, 1024>>>();
    k_transform<<<592, 256>>>(xr, xi);   // position 4: profiled launch
    k_scantop<<<1, 128>>>();
    k_offsets<<<SCB, 1024>>>();
    k_place<<<(NE + 255) / 256, 256>>>(ei);
    k_gather<<<(NN * 32 + 255) / 256, 256>>>(out);
}

// round 6
// speedup vs baseline: 1.0909x; 1.0909x over previous
#include <cuda_runtime.h>
#include <cuda_fp16.h>
#include <math.h>

#define NN 100000
#define NE 1600000
#define DF 64
#define TN 32                 // nodes per transform tile
#define NT2 (NN / TN)         // 3125 tiles
#define SCB 98                // scan blocks: ceil(NN/1024)

typedef unsigned long long ull;

// ---------------- device scratch (static: no allocation allowed) ----------------
__device__ __half g_UVf[NN * 128];  // per node: U[0:64] then Vf[0:64]  (fp16)
__device__ __half g_UVt[NN * 128];  // per node: U[0:64] then Vt[0:64]  (fp16)
__device__ float g_outinv[NN];
__device__ float g_ininv [NN];
__device__ int   g_degout[NN];
__device__ int   g_degin [NN];
__device__ int   g_rs_fwd[NN + 1];
__device__ int   g_rs_rev[NN + 1];
__device__ int   g_cur_fwd[NN];
__device__ int   g_cur_rev[NN];
__device__ int   g_csr_fwd[NE];
__device__ int   g_csr_rev[NE];
__device__ int   g_bsum_fwd[SCB];
__device__ int   g_bsum_rev[SCB];
__device__ int   g_bbase_fwd[SCB];
__device__ int   g_bbase_rev[SCB];
__device__ float g_Wr[DF * DF];
__device__ float g_Wi[DF * DF];
__device__ float g_bias[128];      // [0:64) breal_eff, [64:128) bimag_eff

// ---------------- helpers ----------------
__device__ __forceinline__ void ffma2(ull& acc, ull a, ull b) {
    asm("fma.rn.f32x2 %0, %1, %2, %0;" : "+l"(acc) : "l"(a), "l"(b));
}

__device__ __forceinline__ float2 unpack2(ull v) {
    float2 r;
    asm("mov.b64 {%0, %1}, %2;" : "=f"(r.x), "=f"(r.y) : "l"(v));
    return r;
}

// ---------------- kernels ----------------
// (L1) zero degree counters + build effective weights/biases
__global__ void k_zero_weights(const float* __restrict__ Wr, const float* __restrict__ br,
                               const float* __restrict__ Wi, const float* __restrict__ bi) {
    int i = blockIdx.x * blockDim.x + threadIdx.x;
    if (i < NN) { g_degout[i] = 0; g_degin[i] = 0; }
    if (i < DF * DF) {
        g_Wr[i] = Wr[i] + 0.5f * Wr[4096 + i] + 0.25f * Wr[8192 + i];
        g_Wi[i] = Wi[i] + 0.5f * Wi[4096 + i] + 0.25f * Wi[8192 + i];
    }
    if (i < DF) {
        float bre = br[i] + 0.5f * br[64 + i] + 0.25f * br[128 + i];
        float bie = bi[i] + 0.5f * bi[64 + i] + 0.25f * bi[128 + i];
        g_bias[i]      = bre - bie;
        g_bias[64 + i] = bre + bie;
    }
}

// (L2) degree counting
__global__ void k_deg(const int* __restrict__ ei) {
    int i = blockIdx.x * blockDim.x + threadIdx.x;
    if (i < NE) {
        atomicAdd(&g_degout[ei[i]], 1);
        atomicAdd(&g_degin [ei[NE + i]], 1);
    }
}

// (L3) per-block degree sums + deg^-0.25 normalizers (fused)
__global__ __launch_bounds__(1024) void k_bsum_inv() {
    __shared__ int sf[1024], sr[1024];
    int t = threadIdx.x;
    int i = blockIdx.x * 1024 + t;
    int dout = 0, din = 0;
    if (i < NN) {
        dout = g_degout[i];
        din  = g_degin[i];
        g_outinv[i] = (dout > 0) ? rsqrtf(sqrtf((float)dout)) : 0.0f;
        g_ininv [i] = (din  > 0) ? rsqrtf(sqrtf((float)din )) : 0.0f;
    }
    sf[t] = dout; sr[t] = din;
    __syncthreads();
    for (int off = 512; off > 0; off >>= 1) {
        if (t < off) { sf[t] += sf[t + off]; sr[t] += sr[t + off]; }
        __syncthreads();
    }
    if (t == 0) {
        g_bsum_fwd[blockIdx.x] = sf[0];
        g_bsum_rev[blockIdx.x] = sr[0];
    }
}

// (L4) Fused dense transform, 4-node x 4-output register tile.
//   a = xr@Wr, b = xi@Wi, q = xi@Wr, r = xr@Wi
//   U = 0.5(a-b), Vt = 0.5q, Vf = r + 0.5q
// smem: weights 32KB (XOR float2-swizzle, conflict-free) + x tile 16KB = 48KB.
__global__ __launch_bounds__(128) void k_transform(const float* __restrict__ xr,
                                                   const float* __restrict__ xi) {
    __shared__ __align__(16) float sWr[DF * DF];   // float2 idx: o*32 + ((d2+o)&31)
    __shared__ __align__(16) float sWi[DF * DF];
    __shared__ __align__(16) float sx[TN * 128];   // [node][0:64 xr | 64:128 xi]

    int t = threadIdx.x;
    // stage weights once (swizzled)
    for (int i = t; i < DF * DF; i += 128) {
        int o = i >> 6, d = i & 63;
        int d2 = d >> 1, lo = d & 1;
        int sw = (o * 32 + ((d2 + o) & 31)) * 2 + lo;
        sWr[sw] = g_Wr[i];
        sWi[sw] = g_Wi[i];
    }
    __syncthreads();

    int oq = t & 15;    // output quarter: o = oq + 16j
    int ng = t >> 4;    // node group 0..7: node = ng + 8k

    for (int tile = blockIdx.x; tile < NT2; tile += gridDim.x) {
        int nbase = tile * TN;
        // stage x: 32 nodes x 32 float4 (xr then xi)
        for (int i = t; i < TN * 32; i += 128) {
            int nd = i >> 5, k = i & 31;
            float4 v = (k < 16) ? ((const float4*)xr)[(size_t)(nbase + nd) * 16 + k]
                                : ((const float4*)xi)[(size_t)(nbase + nd) * 16 + (k - 16)];
            ((float4*)sx)[nd * 32 + k] = v;
        }
        __syncthreads();

        ull accA[16], accB[16], accQ[16], accR[16];
        #pragma unroll
        for (int i = 0; i < 16; i++) { accA[i] = 0; accB[i] = 0; accQ[i] = 0; accR[i] = 0; }

        #pragma unroll 2
        for (int d2 = 0; d2 < 32; d2++) {
            ull wr[4], wi[4], xrv[4], xiv[4];
            #pragma unroll
            for (int j = 0; j < 4; j++) {
                int o = oq + j * 16;
                int sw = o * 32 + ((d2 + o) & 31);
                wr[j] = ((const ull*)sWr)[sw];
                wi[j] = ((const ull*)sWi)[sw];
            }
            #pragma unroll
            for (int k = 0; k < 4; k++) {
                int nd = ng + k * 8;
                xrv[k] = ((const ull*)(sx + nd * 128))[d2];
                xiv[k] = ((const ull*)(sx + nd * 128 + 64))[d2];
            }
            #pragma unroll
            for (int k = 0; k < 4; k++) {
                #pragma unroll
                for (int j = 0; j < 4; j++) {
                    ffma2(accA[k * 4 + j], xrv[k], wr[j]);
                    ffma2(accB[k * 4 + j], xiv[k], wi[j]);
                    ffma2(accQ[k * 4 + j], xiv[k], wr[j]);
                    ffma2(accR[k * 4 + j], xrv[k], wi[j]);
                }
            }
        }

        #pragma unroll
        for (int k = 0; k < 4; k++) {
            size_t nb = (size_t)(nbase + ng + k * 8) * 128;
            #pragma unroll
            for (int j = 0; j < 4; j++) {
                float2 fa = unpack2(accA[k * 4 + j]);
                float2 fb = unpack2(accB[k * 4 + j]);
                float2 fq = unpack2(accQ[k * 4 + j]);
                float2 fr = unpack2(accR[k * 4 + j]);
                float a = fa.x + fa.y, b = fb.x + fb.y;
                float q = fq.x + fq.y, r = fr.x + fr.y;
                int o = oq + j * 16;
                __half hU  = __float2half_rn(0.5f * (a - b));
                __half hVf = __float2half_rn(r + 0.5f * q);
                __half hVt = __float2half_rn(0.5f * q);
                g_UVf[nb + o]      = hU;
                g_UVf[nb + 64 + o] = hVf;
                g_UVt[nb + o]      = hU;
                g_UVt[nb + 64 + o] = hVt;
            }
        }
        __syncthreads();
    }
}

// (L5) scan stage 2: exclusive scan of the 98 block sums
__global__ __launch_bounds__(128) void k_scantop() {
    __shared__ int sf[128], sr[128];
    int t = threadIdx.x;
    sf[t] = (t < SCB) ? g_bsum_fwd[t] : 0;
    sr[t] = (t < SCB) ? g_bsum_rev[t] : 0;
    __syncthreads();
    for (int off = 1; off < 128; off <<= 1) {
        int vf = sf[t], vr = sr[t];
        int af = (t >= off) ? sf[t - off] : 0;
        int ar = (t >= off) ? sr[t - off] : 0;
        __syncthreads();
        sf[t] = vf + af; sr[t] = vr + ar;
        __syncthreads();
    }
    if (t < SCB) {
        g_bbase_fwd[t] = (t == 0) ? 0 : sf[t - 1];
        g_bbase_rev[t] = (t == 0) ? 0 : sr[t - 1];
    }
}

// (L6) scan stage 3: in-block exclusive scan + block base -> rs/cur
__global__ __launch_bounds__(1024) void k_offsets() {
    __shared__ int sf[1024], sr[1024];
    int t = threadIdx.x;
    int i = blockIdx.x * 1024 + t;
    int dout = (i < NN) ? g_degout[i] : 0;
    int din  = (i < NN) ? g_degin[i]  : 0;
    sf[t] = dout; sr[t] = din;
    __syncthreads();
    for (int off = 1; off < 1024; off <<= 1) {
        int vf = sf[t], vr = sr[t];
        int af = (t >= off) ? sf[t - off] : 0;
        int ar = (t >= off) ? sr[t - off] : 0;
        __syncthreads();
        sf[t] = vf + af; sr[t] = vr + ar;
        __syncthreads();
    }
    if (i < NN) {
        int of  = g_bbase_fwd[blockIdx.x] + sf[t] - dout;
        int orv = g_bbase_rev[blockIdx.x] + sr[t] - din;
        g_rs_fwd[i] = of;  g_cur_fwd[i] = of;
        g_rs_rev[i] = orv; g_cur_rev[i] = orv;
    }
    if (i == NN - 1) { g_rs_fwd[NN] = NE; g_rs_rev[NN] = NE; }
}

// (L7) CSR placement
__global__ void k_place(const int* __restrict__ ei) {
    int e = blockIdx.x * blockDim.x + threadIdx.x;
    if (e < NE) {
        int row = ei[e];
        int col = ei[NE + e];
        int p = atomicAdd(&g_cur_fwd[row], 1);
        g_csr_fwd[p] = col;
        int q = atomicAdd(&g_cur_rev[col], 1);
        g_csr_rev[q] = row;
    }
}

// (L8) Pull-mode gather (round-4 form: simple loop, one LDG.64/edge-visit)
__global__ __launch_bounds__(256) void k_gather(float* __restrict__ out) {
    int n    = (blockIdx.x * 256 + threadIdx.x) >> 5;
    int lane = threadIdx.x & 31;
    if (n >= NN) return;

    float4 acc = ((const float4*)g_bias)[lane];
    float oinv = g_outinv[n];
    float iinv = g_ininv[n];

    // forward: outgoing edges (row == n), gather UVf[col]
    {
        int s = g_rs_fwd[n], e = g_rs_fwd[n + 1];
        for (int base = s; base < e; base += 32) {
            ull ent = 0;
            if (base + lane < e) {
                int idxl = __ldg(g_csr_fwd + base + lane);
                float w = oinv * __ldg(g_ininv + idxl);
                ent = ((ull)__float_as_uint(w) << 32) | (unsigned)idxl;
            }
            int m = min(32, e - base);
            for (int j = 0; j < m; j++) {
                ull v = __shfl_sync(0xffffffffu, ent, j);
                int   idx = (int)(v & 0xffffffffu);
                float w   = __uint_as_float((unsigned)(v >> 32));
                uint2 pk  = __ldg((const uint2*)(g_UVf + (size_t)idx * 128) + lane);
                float2 f0 = __half22float2(*(const __half2*)&pk.x);
                float2 f1 = __half22float2(*(const __half2*)&pk.y);
                acc.x = fmaf(w, f0.x, acc.x); acc.y = fmaf(w, f0.y, acc.y);
                acc.z = fmaf(w, f1.x, acc.z); acc.w = fmaf(w, f1.y, acc.w);
            }
        }
    }
    // reverse: incoming edges (col == n), gather UVt[row]
    {
        int s = g_rs_rev[n], e = g_rs_rev[n + 1];
        for (int base = s; base < e; base += 32) {
            ull ent = 0;
            if (base + lane < e) {
                int idxl = __ldg(g_csr_rev + base + lane);
                float w = iinv * __ldg(g_outinv + idxl);
                ent = ((ull)__float_as_uint(w) << 32) | (unsigned)idxl;
            }
            int m = min(32, e - base);
            for (int j = 0; j < m; j++) {
                ull v = __shfl_sync(0xffffffffu, ent, j);
                int   idx = (int)(v & 0xffffffffu);
                float w   = __uint_as_float((unsigned)(v >> 32));
                uint2 pk  = __ldg((const uint2*)(g_UVt + (size_t)idx * 128) + lane);
                float2 f0 = __half22float2(*(const __half2*)&pk.x);
                float2 f1 = __half22float2(*(const __half2*)&pk.y);
                acc.x = fmaf(w, f0.x, acc.x); acc.y = fmaf(w, f0.y, acc.y);
                acc.z = fmaf(w, f1.x, acc.z); acc.w = fmaf(w, f1.y, acc.w);
            }
        }
    }

    if (lane < 16) {
        ((float4*)(out + (size_t)n * DF))[lane] = acc;
    } else {
        ((float4*)(out + (size_t)NN * DF + (size_t)n * DF))[lane - 16] = acc;
    }
}

// ---------------- launch ----------------
extern "C" void kernel_launch(void* const* d_in, const int* in_sizes, int n_in,
                              void* d_out, int out_size) {
    const float* xr = (const float*)d_in[0];
    const float* xi = (const float*)d_in[1];
    const int*   ei = (const int*)  d_in[2];
    const float* Wr = (const float*)d_in[3];
    const float* br = (const float*)d_in[4];
    const float* Wi = (const float*)d_in[5];
    const float* bi = (const float*)d_in[6];
    float* out = (float*)d_out;

    k_zero_weights<<<(NN + 255) / 256, 256>>>(Wr, br, Wi, bi);
    k_deg<<<(NE + 255) / 256, 256>>>(ei);
    k_bsum_inv<<<SCB, 1024>>>();
    k_transform<<<296, 128>>>(xr, xi);   // position 4: profiled launch
    k_scantop<<<1, 128>>>();
    k_offsets<<<SCB, 1024>>>();
    k_place<<<(NE + 255) / 256, 256>>>(ei);
    k_gather<<<(NN * 32 + 255) / 256, 256>>>(out);
}

// round 7
// speedup vs baseline: 1.1801x; 1.0818x over previous
#include <cuda_runtime.h>
#include <cuda_fp16.h>
#include <math.h>

#define NN 100000
#define NE 1600000
#define DF 64
#define TN 32                 // nodes per transform tile
#define NT2 (NN / TN)         // 3125 tiles
#define SCB 98                // scan blocks: ceil(NN/1024)
#define WP 33                 // padded weight row stride in float2 units

typedef unsigned long long ull;

// ---------------- device scratch (static: no allocation allowed) ----------------
__device__ __half g_UVf[NN * 128];  // per node: U[0:64] then Vf[0:64]  (fp16)
__device__ __half g_UVt[NN * 128];  // per node: U[0:64] then Vt[0:64]  (fp16)
__device__ float g_outinv[NN];
__device__ float g_ininv [NN];
__device__ int   g_degout[NN];
__device__ int   g_degin [NN];
__device__ int   g_rs_fwd[NN + 1];
__device__ int   g_rs_rev[NN + 1];
__device__ int   g_cur_fwd[NN];
__device__ int   g_cur_rev[NN];
__device__ int   g_csr_fwd[NE];
__device__ int   g_csr_rev[NE];
__device__ int   g_bsum_fwd[SCB];
__device__ int   g_bsum_rev[SCB];
__device__ int   g_bbase_fwd[SCB];
__device__ int   g_bbase_rev[SCB];
__device__ float g_Wr[DF * DF];
__device__ float g_Wi[DF * DF];
__device__ float g_bias[128];      // [0:64) breal_eff, [64:128) bimag_eff

// ---------------- helpers ----------------
__device__ __forceinline__ void ffma2(ull& acc, ull a, ull b) {
    asm("fma.rn.f32x2 %0, %1, %2, %0;" : "+l"(acc) : "l"(a), "l"(b));
}

__device__ __forceinline__ float2 unpack2(ull v) {
    float2 r;
    asm("mov.b64 {%0, %1}, %2;" : "=f"(r.x), "=f"(r.y) : "l"(v));
    return r;
}

// ---------------- kernels ----------------
// (L1) zero degree counters + build effective weights/biases
__global__ void k_zero_weights(const float* __restrict__ Wr, const float* __restrict__ br,
                               const float* __restrict__ Wi, const float* __restrict__ bi) {
    int i = blockIdx.x * blockDim.x + threadIdx.x;
    if (i < NN) { g_degout[i] = 0; g_degin[i] = 0; }
    if (i < DF * DF) {
        g_Wr[i] = Wr[i] + 0.5f * Wr[4096 + i] + 0.25f * Wr[8192 + i];
        g_Wi[i] = Wi[i] + 0.5f * Wi[4096 + i] + 0.25f * Wi[8192 + i];
    }
    if (i < DF) {
        float bre = br[i] + 0.5f * br[64 + i] + 0.25f * br[128 + i];
        float bie = bi[i] + 0.5f * bi[64 + i] + 0.25f * bi[128 + i];
        g_bias[i]      = bre - bie;
        g_bias[64 + i] = bre + bie;
    }
}

// (L2) degree counting
__global__ void k_deg(const int* __restrict__ ei) {
    int i = blockIdx.x * blockDim.x + threadIdx.x;
    if (i < NE) {
        atomicAdd(&g_degout[ei[i]], 1);
        atomicAdd(&g_degin [ei[NE + i]], 1);
    }
}

// (L3) per-block degree sums + deg^-0.25 normalizers (fused)
__global__ __launch_bounds__(1024) void k_bsum_inv() {
    __shared__ int sf[1024], sr[1024];
    int t = threadIdx.x;
    int i = blockIdx.x * 1024 + t;
    int dout = 0, din = 0;
    if (i < NN) {
        dout = g_degout[i];
        din  = g_degin[i];
        g_outinv[i] = (dout > 0) ? rsqrtf(sqrtf((float)dout)) : 0.0f;
        g_ininv [i] = (din  > 0) ? rsqrtf(sqrtf((float)din )) : 0.0f;
    }
    sf[t] = dout; sr[t] = din;
    __syncthreads();
    for (int off = 512; off > 0; off >>= 1) {
        if (t < off) { sf[t] += sf[t + off]; sr[t] += sr[t + off]; }
        __syncthreads();
    }
    if (t == 0) {
        g_bsum_fwd[blockIdx.x] = sf[0];
        g_bsum_rev[blockIdx.x] = sr[0];
    }
}

// (L4) Fused dense transform, 4-node x 4-output register tile.
// 3-accumulator form with negated Wi:
//   accUM = xr@Wr + xi@(-Wi) = a - b
//   accQ  = xi@Wr            = q
//   accRn = xr@(-Wi)         = -r
//   U = 0.5*accUM, Vt = 0.5*accQ, Vf = -accRn + 0.5*accQ
// Weights in padded float2 layout (stride 33): bank = (o+d2)&31, conflict-free,
// and d2-loop addresses strength-reduce to LDS [ptr + imm] (no ALU swizzle).
__global__ __launch_bounds__(128, 3) void k_transform(const float* __restrict__ xr,
                                                      const float* __restrict__ xi) {
    __shared__ __align__(16) float sWr [DF * WP * 2];  // float2 unit: o*WP + d2
    __shared__ __align__(16) float sWin[DF * WP * 2];  // -Wi_eff
    __shared__ __align__(16) float sx[TN * 128];       // [node][0:64 xr | 64:128 xi]

    int t = threadIdx.x;
    for (int i = t; i < DF * DF; i += 128) {
        int o = i >> 6, d = i & 63;
        int u = (o * WP + (d >> 1)) * 2 + (d & 1);
        sWr [u] =  g_Wr[i];
        sWin[u] = -g_Wi[i];
    }
    __syncthreads();

    int oq = t & 15;    // output quarter: o = oq + 16j
    int ng = t >> 4;    // node group 0..7: node = ng + 8k

    const ull* wrp[4];
    const ull* wip[4];
    #pragma unroll
    for (int j = 0; j < 4; j++) {
        int o = oq + j * 16;
        wrp[j] = (const ull*)sWr  + o * WP;
        wip[j] = (const ull*)sWin + o * WP;
    }

    for (int tile = blockIdx.x; tile < NT2; tile += gridDim.x) {
        int nbase = tile * TN;
        // stage x: 32 nodes x 32 float4 (xr then xi)
        for (int i = t; i < TN * 32; i += 128) {
            int nd = i >> 5, k = i & 31;
            float4 v = (k < 16) ? ((const float4*)xr)[(size_t)(nbase + nd) * 16 + k]
                                : ((const float4*)xi)[(size_t)(nbase + nd) * 16 + (k - 16)];
            ((float4*)sx)[nd * 32 + k] = v;
        }
        __syncthreads();

        ull accUM[16], accQ[16], accRn[16];
        #pragma unroll
        for (int i = 0; i < 16; i++) { accUM[i] = 0; accQ[i] = 0; accRn[i] = 0; }

        #pragma unroll 4
        for (int d2 = 0; d2 < 32; d2++) {
            ull wr[4], wi[4], xrv[4], xiv[4];
            #pragma unroll
            for (int j = 0; j < 4; j++) {
                wr[j] = wrp[j][d2];
                wi[j] = wip[j][d2];
            }
            #pragma unroll
            for (int k = 0; k < 4; k++) {
                int nd = ng + k * 8;
                xrv[k] = ((const ull*)(sx + nd * 128))[d2];
                xiv[k] = ((const ull*)(sx + nd * 128 + 64))[d2];
            }
            #pragma unroll
            for (int k = 0; k < 4; k++) {
                #pragma unroll
                for (int j = 0; j < 4; j++) {
                    ffma2(accUM[k * 4 + j], xrv[k], wr[j]);
                    ffma2(accUM[k * 4 + j], xiv[k], wi[j]);
                    ffma2(accQ [k * 4 + j], xiv[k], wr[j]);
                    ffma2(accRn[k * 4 + j], xrv[k], wi[j]);
                }
            }
        }

        #pragma unroll
        for (int k = 0; k < 4; k++) {
            size_t nb = (size_t)(nbase + ng + k * 8) * 128;
            #pragma unroll
            for (int j = 0; j < 4; j++) {
                float2 fu = unpack2(accUM[k * 4 + j]);
                float2 fq = unpack2(accQ [k * 4 + j]);
                float2 fr = unpack2(accRn[k * 4 + j]);
                float um = fu.x + fu.y;            // a - b
                float q  = fq.x + fq.y;
                float r  = -(fr.x + fr.y);
                int o = oq + j * 16;
                __half hU  = __float2half_rn(0.5f * um);
                __half hVf = __float2half_rn(r + 0.5f * q);
                __half hVt = __float2half_rn(0.5f * q);
                g_UVf[nb + o]      = hU;
                g_UVf[nb + 64 + o] = hVf;
                g_UVt[nb + o]      = hU;
                g_UVt[nb + 64 + o] = hVt;
            }
        }
        __syncthreads();
    }
}

// (L5) scan stage 2: exclusive scan of the 98 block sums
__global__ __launch_bounds__(128) void k_scantop() {
    __shared__ int sf[128], sr[128];
    int t = threadIdx.x;
    sf[t] = (t < SCB) ? g_bsum_fwd[t] : 0;
    sr[t] = (t < SCB) ? g_bsum_rev[t] : 0;
    __syncthreads();
    for (int off = 1; off < 128; off <<= 1) {
        int vf = sf[t], vr = sr[t];
        int af = (t >= off) ? sf[t - off] : 0;
        int ar = (t >= off) ? sr[t - off] : 0;
        __syncthreads();
        sf[t] = vf + af; sr[t] = vr + ar;
        __syncthreads();
    }
    if (t < SCB) {
        g_bbase_fwd[t] = (t == 0) ? 0 : sf[t - 1];
        g_bbase_rev[t] = (t == 0) ? 0 : sr[t - 1];
    }
}

// (L6) scan stage 3: in-block exclusive scan + block base -> rs/cur
__global__ __launch_bounds__(1024) void k_offsets() {
    __shared__ int sf[1024], sr[1024];
    int t = threadIdx.x;
    int i = blockIdx.x * 1024 + t;
    int dout = (i < NN) ? g_degout[i] : 0;
    int din  = (i < NN) ? g_degin[i]  : 0;
    sf[t] = dout; sr[t] = din;
    __syncthreads();
    for (int off = 1; off < 1024; off <<= 1) {
        int vf = sf[t], vr = sr[t];
        int af = (t >= off) ? sf[t - off] : 0;
        int ar = (t >= off) ? sr[t - off] : 0;
        __syncthreads();
        sf[t] = vf + af; sr[t] = vr + ar;
        __syncthreads();
    }
    if (i < NN) {
        int of  = g_bbase_fwd[blockIdx.x] + sf[t] - dout;
        int orv = g_bbase_rev[blockIdx.x] + sr[t] - din;
        g_rs_fwd[i] = of;  g_cur_fwd[i] = of;
        g_rs_rev[i] = orv; g_cur_rev[i] = orv;
    }
    if (i == NN - 1) { g_rs_fwd[NN] = NE; g_rs_rev[NN] = NE; }
}

// (L7) CSR placement
__global__ void k_place(const int* __restrict__ ei) {
    int e = blockIdx.x * blockDim.x + threadIdx.x;
    if (e < NE) {
        int row = ei[e];
        int col = ei[NE + e];
        int p = atomicAdd(&g_cur_fwd[row], 1);
        g_csr_fwd[p] = col;
        int q = atomicAdd(&g_cur_rev[col], 1);
        g_csr_rev[q] = row;
    }
}

// (L8) Pull-mode gather (one LDG.64 per edge-visit, half-warp split outputs)
__global__ __launch_bounds__(256) void k_gather(float* __restrict__ out) {
    int n    = (blockIdx.x * 256 + threadIdx.x) >> 5;
    int lane = threadIdx.x & 31;
    if (n >= NN) return;

    float4 acc = ((const float4*)g_bias)[lane];
    float oinv = g_outinv[n];
    float iinv = g_ininv[n];

    // forward: outgoing edges (row == n), gather UVf[col]
    {
        int s = g_rs_fwd[n], e = g_rs_fwd[n + 1];
        for (int base = s; base < e; base += 32) {
            ull ent = 0;
            if (base + lane < e) {
                int idxl = __ldg(g_csr_fwd + base + lane);
                float w = oinv * __ldg(g_ininv + idxl);
                ent = ((ull)__float_as_uint(w) << 32) | (unsigned)idxl;
            }
            int m = min(32, e - base);
            for (int j = 0; j < m; j++) {
                ull v = __shfl_sync(0xffffffffu, ent, j);
                int   idx = (int)(v & 0xffffffffu);
                float w   = __uint_as_float((unsigned)(v >> 32));
                uint2 pk  = __ldg((const uint2*)(g_UVf + (size_t)idx * 128) + lane);
                float2 f0 = __half22float2(*(const __half2*)&pk.x);
                float2 f1 = __half22float2(*(const __half2*)&pk.y);
                acc.x = fmaf(w, f0.x, acc.x); acc.y = fmaf(w, f0.y, acc.y);
                acc.z = fmaf(w, f1.x, acc.z); acc.w = fmaf(w, f1.y, acc.w);
            }
        }
    }
    // reverse: incoming edges (col == n), gather UVt[row]
    {
        int s = g_rs_rev[n], e = g_rs_rev[n + 1];
        for (int base = s; base < e; base += 32) {
            ull ent = 0;
            if (base + lane < e) {
                int idxl = __ldg(g_csr_rev + base + lane);
                float w = iinv * __ldg(g_outinv + idxl);
                ent = ((ull)__float_as_uint(w) << 32) | (unsigned)idxl;
            }
            int m = min(32, e - base);
            for (int j = 0; j < m; j++) {
                ull v = __shfl_sync(0xffffffffu, ent, j);
                int   idx = (int)(v & 0xffffffffu);
                float w   = __uint_as_float((unsigned)(v >> 32));
                uint2 pk  = __ldg((const uint2*)(g_UVt + (size_t)idx * 128) + lane);
                float2 f0 = __half22float2(*(const __half2*)&pk.x);
                float2 f1 = __half22float2(*(const __half2*)&pk.y);
                acc.x = fmaf(w, f0.x, acc.x); acc.y = fmaf(w, f0.y, acc.y);
                acc.z = fmaf(w, f1.x, acc.z); acc.w = fmaf(w, f1.y, acc.w);
            }
        }
    }

    if (lane < 16) {
        ((float4*)(out + (size_t)n * DF))[lane] = acc;
    } else {
        ((float4*)(out + (size_t)NN * DF + (size_t)n * DF))[lane - 16] = acc;
    }
}

// ---------------- launch ----------------
extern "C" void kernel_launch(void* const* d_in, const int* in_sizes, int n_in,
                              void* d_out, int out_size) {
    const float* xr = (const float*)d_in[0];
    const float* xi = (const float*)d_in[1];
    const int*   ei = (const int*)  d_in[2];
    const float* Wr = (const float*)d_in[3];
    const float* br = (const float*)d_in[4];
    const float* Wi = (const float*)d_in[5];
    const float* bi = (const float*)d_in[6];
    float* out = (float*)d_out;

    k_zero_weights<<<(NN + 255) / 256, 256>>>(Wr, br, Wi, bi);
    k_deg<<<(NE + 255) / 256, 256>>>(ei);
    k_bsum_inv<<<SCB, 1024>>>();
    k_transform<<<444, 128>>>(xr, xi);   // position 4: profiled launch
    k_scantop<<<1, 128>>>();
    k_offsets<<<SCB, 1024>>>();
    k_place<<<(NE + 255) / 256, 256>>>(ei);
    k_gather<<<(NN * 32 + 255) / 256, 256>>>(out);
}

// round 8
// speedup vs baseline: 1.3715x; 1.1622x over previous
#include <cuda_runtime.h>
#include <cuda_fp16.h>
#include <math.h>

#define NN 100000
#define NE 1600000
#define DF 64
#define SCB 98                // scan blocks: ceil(NN/1024)
#define XTS 136               // padded smem row stride in halfs (X and W tiles)
#define NTILE 1563            // ceil(NN/64)

typedef unsigned long long ull;

// ---------------- device scratch (static: no allocation allowed) ----------------
__device__ __half g_UVf[NN * 128];  // per node: U[0:64] then Vf[0:64]  (fp16)
__device__ __half g_UVt[NN * 128];  // per node: U[0:64] then Vt[0:64]  (fp16)
__device__ __half g_Wcat[192 * 128];// fused weights: rows = out col, cols = [xr|xi]
__device__ float g_outinv[NN];
__device__ float g_ininv [NN];
__device__ int   g_degout[NN];
__device__ int   g_degin [NN];
__device__ int   g_rs_fwd[NN + 1];
__device__ int   g_rs_rev[NN + 1];
__device__ int   g_cur_fwd[NN];
__device__ int   g_cur_rev[NN];
__device__ int   g_csr_fwd[NE];
__device__ int   g_csr_rev[NE];
__device__ int   g_bsum_fwd[SCB];
__device__ int   g_bsum_rev[SCB];
__device__ int   g_bbase_fwd[SCB];
__device__ int   g_bbase_rev[SCB];
__device__ float g_bias[128];       // [0:64) breal_eff, [64:128) bimag_eff

// ---------------- helpers ----------------
__device__ __forceinline__ unsigned smem_u32(const void* p) {
    unsigned a;
    asm("{ .reg .u64 t; cvta.to.shared.u64 t, %1; cvt.u32.u64 %0, t; }" : "=r"(a) : "l"(p));
    return a;
}

// ---------------- kernels ----------------
// (L1) zero degrees + build fused fp16 weight matrix Wcat + biases
//   Wcat rows gc:
//     gc<64   (U):  [0.5*WrE | -0.5*WiE]
//     64..127 (Vf): [WiE     |  0.5*WrE]
//     128..191(Vt): [0       |  0.5*WrE]
__global__ void k_zero_weights(const float* __restrict__ Wr, const float* __restrict__ br,
                               const float* __restrict__ Wi, const float* __restrict__ bi) {
    int i = blockIdx.x * blockDim.x + threadIdx.x;
    if (i < NN) { g_degout[i] = 0; g_degin[i] = 0; }
    if (i < 192 * 128) {
        int gc = i >> 7, d2 = i & 127;
        float val = 0.0f;
        if (gc < 64) {
            int o = gc;
            if (d2 < 64) {
                int u = o * 64 + d2;
                val = 0.5f * (Wr[u] + 0.5f * Wr[4096 + u] + 0.25f * Wr[8192 + u]);
            } else {
                int u = o * 64 + (d2 - 64);
                val = -0.5f * (Wi[u] + 0.5f * Wi[4096 + u] + 0.25f * Wi[8192 + u]);
            }
        } else if (gc < 128) {
            int j = gc - 64;
            if (d2 < 64) {
                int u = j * 64 + d2;
                val = Wi[u] + 0.5f * Wi[4096 + u] + 0.25f * Wi[8192 + u];
            } else {
                int u = j * 64 + (d2 - 64);
                val = 0.5f * (Wr[u] + 0.5f * Wr[4096 + u] + 0.25f * Wr[8192 + u]);
            }
        } else {
            int j = gc - 128;
            if (d2 >= 64) {
                int u = j * 64 + (d2 - 64);
                val = 0.5f * (Wr[u] + 0.5f * Wr[4096 + u] + 0.25f * Wr[8192 + u]);
            }
        }
        g_Wcat[i] = __float2half_rn(val);
    }
    if (i < DF) {
        float bre = br[i] + 0.5f * br[64 + i] + 0.25f * br[128 + i];
        float bie = bi[i] + 0.5f * bi[64 + i] + 0.25f * bi[128 + i];
        g_bias[i]      = bre - bie;
        g_bias[64 + i] = bre + bie;
    }
}

// (L2) degree counting
__global__ void k_deg(const int* __restrict__ ei) {
    int i = blockIdx.x * blockDim.x + threadIdx.x;
    if (i < NE) {
        atomicAdd(&g_degout[ei[i]], 1);
        atomicAdd(&g_degin [ei[NE + i]], 1);
    }
}

// (L3) per-block degree sums + deg^-0.25 normalizers (fused)
__global__ __launch_bounds__(1024) void k_bsum_inv() {
    __shared__ int sf[1024], sr[1024];
    int t = threadIdx.x;
    int i = blockIdx.x * 1024 + t;
    int dout = 0, din = 0;
    if (i < NN) {
        dout = g_degout[i];
        din  = g_degin[i];
        g_outinv[i] = (dout > 0) ? rsqrtf(sqrtf((float)dout)) : 0.0f;
        g_ininv [i] = (din  > 0) ? rsqrtf(sqrtf((float)din )) : 0.0f;
    }
    sf[t] = dout; sr[t] = din;
    __syncthreads();
    for (int off = 512; off > 0; off >>= 1) {
        if (t < off) { sf[t] += sf[t + off]; sr[t] += sr[t + off]; }
        __syncthreads();
    }
    if (t == 0) {
        g_bsum_fwd[blockIdx.x] = sf[0];
        g_bsum_rev[blockIdx.x] = sr[0];
    }
}

// (L4) HMMA transform: Y[64 nodes, 96 cols] = X_tile @ Wcat_chunk^T per block.
// blockIdx.x = node tile (64 nodes), blockIdx.y = col chunk (96 of 192).
// 8 warps: warp w -> nodes [16*(w&3)..+16), cols [48*(w>>2)..+48).
// A via ldmatrix.x4 (row-major X), B via ldmatrix.x2 ([n][k] rows of Wcat).
__global__ __launch_bounds__(256) void k_transform(const float* __restrict__ xr,
                                                   const float* __restrict__ xi) {
    __shared__ __align__(16) __half sX[64 * XTS];   // [node][0:64 xr | 64:128 xi]
    __shared__ __align__(16) __half sW[96 * XTS];   // [local col][128 k]

    int t    = threadIdx.x;
    int lane = t & 31;
    int w    = t >> 5;
    int tilebase = blockIdx.x * 64;
    int chunk    = blockIdx.y;            // 0 or 1

    // stage X tile: 64 nodes x 32 float4 (16 xr + 16 xi), fp32 -> fp16
    #pragma unroll
    for (int it = 0; it < 8; it++) {
        int idx = t + it * 256;           // 0..2047
        int nd = idx >> 5, k = idx & 31;
        int node = tilebase + nd;
        float4 v = make_float4(0.f, 0.f, 0.f, 0.f);
        if (node < NN)
            v = (k < 16) ? ((const float4*)xr)[(size_t)node * 16 + k]
                         : ((const float4*)xi)[(size_t)node * 16 + (k - 16)];
        __half2 h0 = __floats2half2_rn(v.x, v.y);
        __half2 h1 = __floats2half2_rn(v.z, v.w);
        *(uint2*)(sX + nd * XTS + k * 4) = make_uint2(*(unsigned*)&h0, *(unsigned*)&h1);
    }
    // stage W chunk: 96 rows x 128 halfs (as uint2 = 4 halfs)
    #pragma unroll
    for (int it = 0; it < 12; it++) {
        int idx = t + it * 256;           // 0..3071
        int r = idx >> 5, c = idx & 31;
        uint2 v = ((const uint2*)g_Wcat)[((size_t)(96 * chunk + r) << 5) + c];
        *(uint2*)(sW + r * XTS + c * 4) = v;
    }
    __syncthreads();

    int ngrp = w & 3;                     // node group
    int ns   = w >> 2;                    // col half
    int nodebase = 16 * ngrp;
    int colbase  = 48 * ns;

    // ldmatrix addresses
    unsigned a_addr = smem_u32(sX) +
        (unsigned)(((nodebase + (lane & 15)) * XTS + ((lane >> 4) * 8)) * 2);
    int lb = lane & 15;
    unsigned b_addr0 = smem_u32(sW) +
        (unsigned)(((colbase + (lb & 7)) * XTS + ((lb >> 3) * 8)) * 2);

    float acc[6][4];
    #pragma unroll
    for (int nt = 0; nt < 6; nt++)
        #pragma unroll
        for (int q = 0; q < 4; q++) acc[nt][q] = 0.0f;

    #pragma unroll
    for (int kk = 0; kk < 8; kk++) {
        unsigned a0, a1, a2, a3;
        asm volatile("ldmatrix.sync.aligned.m8n8.x4.shared.b16 {%0,%1,%2,%3}, [%4];"
                     : "=r"(a0), "=r"(a1), "=r"(a2), "=r"(a3)
                     : "r"(a_addr + kk * 32));
        #pragma unroll
        for (int nt = 0; nt < 6; nt++) {
            unsigned b0, b1;
            asm volatile("ldmatrix.sync.aligned.m8n8.x2.shared.b16 {%0,%1}, [%2];"
                         : "=r"(b0), "=r"(b1)
                         : "r"(b_addr0 + nt * (8 * XTS * 2) + kk * 32));
            asm volatile("mma.sync.aligned.m16n8k16.row.col.f32.f16.f16.f32 "
                         "{%0,%1,%2,%3}, {%4,%5,%6,%7}, {%8,%9}, {%0,%1,%2,%3};"
                         : "+f"(acc[nt][0]), "+f"(acc[nt][1]),
                           "+f"(acc[nt][2]), "+f"(acc[nt][3])
                         : "r"(a0), "r"(a1), "r"(a2), "r"(a3), "r"(b0), "r"(b1));
        }
    }

    // epilogue: direct fp16 stores, no cross-combination
    int r0 = tilebase + nodebase + (lane >> 2);
    int r1 = r0 + 8;
    #pragma unroll
    for (int nt = 0; nt < 6; nt++) {
        int gc = 96 * chunk + colbase + 8 * nt + 2 * (lane & 3);
        __half2 lo = __floats2half2_rn(acc[nt][0], acc[nt][1]);
        __half2 hi = __floats2half2_rn(acc[nt][2], acc[nt][3]);
        if (r0 < NN) {
            if (gc < 128) *(__half2*)(g_UVf + (size_t)r0 * 128 + gc) = lo;
            if (gc < 64)  *(__half2*)(g_UVt + (size_t)r0 * 128 + gc) = lo;
            if (gc >= 128)*(__half2*)(g_UVt + (size_t)r0 * 128 + gc - 64) = lo;
        }
        if (r1 < NN) {
            if (gc < 128) *(__half2*)(g_UVf + (size_t)r1 * 128 + gc) = hi;
            if (gc < 64)  *(__half2*)(g_UVt + (size_t)r1 * 128 + gc) = hi;
            if (gc >= 128)*(__half2*)(g_UVt + (size_t)r1 * 128 + gc - 64) = hi;
        }
    }
}

// (L5) scan stage 2: exclusive scan of the 98 block sums
__global__ __launch_bounds__(128) void k_scantop() {
    __shared__ int sf[128], sr[128];
    int t = threadIdx.x;
    sf[t] = (t < SCB) ? g_bsum_fwd[t] : 0;
    sr[t] = (t < SCB) ? g_bsum_rev[t] : 0;
    __syncthreads();
    for (int off = 1; off < 128; off <<= 1) {
        int vf = sf[t], vr = sr[t];
        int af = (t >= off) ? sf[t - off] : 0;
        int ar = (t >= off) ? sr[t - off] : 0;
        __syncthreads();
        sf[t] = vf + af; sr[t] = vr + ar;
        __syncthreads();
    }
    if (t < SCB) {
        g_bbase_fwd[t] = (t == 0) ? 0 : sf[t - 1];
        g_bbase_rev[t] = (t == 0) ? 0 : sr[t - 1];
    }
}

// (L6) scan stage 3: in-block exclusive scan + block base -> rs/cur
__global__ __launch_bounds__(1024) void k_offsets() {
    __shared__ int sf[1024], sr[1024];
    int t = threadIdx.x;
    int i = blockIdx.x * 1024 + t;
    int dout = (i < NN) ? g_degout[i] : 0;
    int din  = (i < NN) ? g_degin[i]  : 0;
    sf[t] = dout; sr[t] = din;
    __syncthreads();
    for (int off = 1; off < 1024; off <<= 1) {
        int vf = sf[t], vr = sr[t];
        int af = (t >= off) ? sf[t - off] : 0;
        int ar = (t >= off) ? sr[t - off] : 0;
        __syncthreads();
        sf[t] = vf + af; sr[t] = vr + ar;
        __syncthreads();
    }
    if (i < NN) {
        int of  = g_bbase_fwd[blockIdx.x] + sf[t] - dout;
        int orv = g_bbase_rev[blockIdx.x] + sr[t] - din;
        g_rs_fwd[i] = of;  g_cur_fwd[i] = of;
        g_rs_rev[i] = orv; g_cur_rev[i] = orv;
    }
    if (i == NN - 1) { g_rs_fwd[NN] = NE; g_rs_rev[NN] = NE; }
}

// (L7) CSR placement
__global__ void k_place(const int* __restrict__ ei) {
    int e = blockIdx.x * blockDim.x + threadIdx.x;
    if (e < NE) {
        int row = ei[e];
        int col = ei[NE + e];
        int p = atomicAdd(&g_cur_fwd[row], 1);
        g_csr_fwd[p] = col;
        int q = atomicAdd(&g_cur_rev[col], 1);
        g_csr_rev[q] = row;
    }
}

// (L8) Pull-mode gather (one LDG.64 per edge-visit, half-warp split outputs)
__global__ __launch_bounds__(256) void k_gather(float* __restrict__ out) {
    int n    = (blockIdx.x * 256 + threadIdx.x) >> 5;
    int lane = threadIdx.x & 31;
    if (n >= NN) return;

    float4 acc = ((const float4*)g_bias)[lane];
    float oinv = g_outinv[n];
    float iinv = g_ininv[n];

    // forward: outgoing edges (row == n), gather UVf[col]
    {
        int s = g_rs_fwd[n], e = g_rs_fwd[n + 1];
        for (int base = s; base < e; base += 32) {
            ull ent = 0;
            if (base + lane < e) {
                int idxl = __ldg(g_csr_fwd + base + lane);
                float w = oinv * __ldg(g_ininv + idxl);
                ent = ((ull)__float_as_uint(w) << 32) | (unsigned)idxl;
            }
            int m = min(32, e - base);
            for (int j = 0; j < m; j++) {
                ull v = __shfl_sync(0xffffffffu, ent, j);
                int   idx = (int)(v & 0xffffffffu);
                float w   = __uint_as_float((unsigned)(v >> 32));
                uint2 pk  = __ldg((const uint2*)(g_UVf + (size_t)idx * 128) + lane);
                float2 f0 = __half22float2(*(const __half2*)&pk.x);
                float2 f1 = __half22float2(*(const __half2*)&pk.y);
                acc.x = fmaf(w, f0.x, acc.x); acc.y = fmaf(w, f0.y, acc.y);
                acc.z = fmaf(w, f1.x, acc.z); acc.w = fmaf(w, f1.y, acc.w);
            }
        }
    }
    // reverse: incoming edges (col == n), gather UVt[row]
    {
        int s = g_rs_rev[n], e = g_rs_rev[n + 1];
        for (int base = s; base < e; base += 32) {
            ull ent = 0;
            if (base + lane < e) {
                int idxl = __ldg(g_csr_rev + base + lane);
                float w = iinv * __ldg(g_outinv + idxl);
                ent = ((ull)__float_as_uint(w) << 32) | (unsigned)idxl;
            }
            int m = min(32, e - base);
            for (int j = 0; j < m; j++) {
                ull v = __shfl_sync(0xffffffffu, ent, j);
                int   idx = (int)(v & 0xffffffffu);
                float w   = __uint_as_float((unsigned)(v >> 32));
                uint2 pk  = __ldg((const uint2*)(g_UVt + (size_t)idx * 128) + lane);
                float2 f0 = __half22float2(*(const __half2*)&pk.x);
                float2 f1 = __half22float2(*(const __half2*)&pk.y);
                acc.x = fmaf(w, f0.x, acc.x); acc.y = fmaf(w, f0.y, acc.y);
                acc.z = fmaf(w, f1.x, acc.z); acc.w = fmaf(w, f1.y, acc.w);
            }
        }
    }

    if (lane < 16) {
        ((float4*)(out + (size_t)n * DF))[lane] = acc;
    } else {
        ((float4*)(out + (size_t)NN * DF + (size_t)n * DF))[lane - 16] = acc;
    }
}

// ---------------- launch ----------------
extern "C" void kernel_launch(void* const* d_in, const int* in_sizes, int n_in,
                              void* d_out, int out_size) {
    const float* xr = (const float*)d_in[0];
    const float* xi = (const float*)d_in[1];
    const int*   ei = (const int*)  d_in[2];
    const float* Wr = (const float*)d_in[3];
    const float* br = (const float*)d_in[4];
    const float* Wi = (const float*)d_in[5];
    const float* bi = (const float*)d_in[6];
    float* out = (float*)d_out;

    k_zero_weights<<<(NN + 255) / 256, 256>>>(Wr, br, Wi, bi);
    k_deg<<<(NE + 255) / 256, 256>>>(ei);
    k_bsum_inv<<<SCB, 1024>>>();
    k_transform<<<dim3(NTILE, 2), 256>>>(xr, xi);   // position 4: profiled launch
    k_scantop<<<1, 128>>>();
    k_offsets<<<SCB, 1024>>>();
    k_place<<<(NE + 255) / 256, 256>>>(ei);
    k_gather<<<(NN * 32 + 255) / 256, 256>>>(out);
}